// round 11
// baseline (speedup 1.0000x reference)
#include <cuda_runtime.h>
#include <cstdint>

#define WIDTH  1024
#define HALF   512
#define DEPTH  8
#define BDEPTH 10
#define BATCH  65536

typedef unsigned long long ull;

// ============================ Geometry ============================
// lane = 5 bits, slot v = 5 bits, rows: 4 per warp packed as val[v*2+h] (f32x2).
// Initial mapping: lane bit k <-> p bit k+2 ; reg slot r <-> p bits {0,1,7,8,9}[r].
// Each layer butterflies p bits 9..0 in order. Bits resident in reg slots are
// butterflied locally; bits in lanes are first SWAPPED into a reg slot via an
// anti-diagonal warp exchange (64 SHFL.32 instead of 128 for a direct lane
// butterfly). Slot eviction follows a compile-time Belady schedule. Tables are
// baked per (layer, step) against the evolving bit->location mapping.

struct Sched {
    int slot[DEPTH][BDEPTH];        // reg slot butterflied at (L,t)
    int swpl[DEPTH][BDEPTH];        // lane bit swapped in first, or -1
    int lpos[DEPTH][BDEPTH][5];     // mapping AFTER swap, at butterfly time
    int rpos[DEPTH][BDEPTH][5];
    int q_lpos[DEPTH][5];           // mapping at end of layer (for quintic)
    int q_rpos[DEPTH][5];
    int nrest;                      // restore swaps after last layer
    int rest_k[12];
    int rest_r[12];
    int fin_rpos[5];                // reg mapping after restore (lanes = {2..6})
    int store_ph[8];                // store: high-bit offset per group
    int store_v[8][4];              // store: val slot per group/component
};

constexpr Sched make_sched() {
    Sched S{};
    int lpos[5] = {2, 3, 4, 5, 6};
    int rpos[5] = {0, 1, 7, 8, 9};
    for (int L = 0; L < DEPTH; L++) {
        for (int t = 0; t < BDEPTH; t++) {
            int b = 9 - t;
            int r = -1, k = -1;
            for (int i = 0; i < 5; i++) if (rpos[i] == b) r = i;
            if (r < 0) {
                for (int i = 0; i < 5; i++) if (lpos[i] == b) k = i;
                // Belady: evict slot whose bit is needed furthest in the future
                int best = 0, bestd = -1;
                for (int i = 0; i < 5; i++) {
                    int bit = rpos[i];
                    int d = -1;
                    for (int tt = t + 1; tt < BDEPTH; tt++)
                        if (9 - tt == bit) { d = tt - (t + 1); break; }
                    if (d < 0) d = (BDEPTH - (t + 1)) + (9 - bit);
                    if (d > bestd) { bestd = d; best = i; }
                }
                r = best;
                int tmp = lpos[k]; lpos[k] = rpos[r]; rpos[r] = tmp;
            }
            S.slot[L][t] = r;
            S.swpl[L][t] = k;
            for (int i = 0; i < 5; i++) { S.lpos[L][t][i] = lpos[i]; S.rpos[L][t][i] = rpos[i]; }
        }
        for (int i = 0; i < 5; i++) { S.q_lpos[L][i] = lpos[i]; S.q_rpos[L][i] = rpos[i]; }
    }
    // restore lane bits to {2,3,4,5,6} (reg-slot permutation handled by store tables)
    int n = 0;
    for (int guard = 0; guard < 12; guard++) {
        int k = -1;
        for (int i = 0; i < 5; i++) if (lpos[i] != i + 2) { k = i; break; }
        if (k < 0) break;
        int want = k + 2;
        int r = -1;
        for (int i = 0; i < 5; i++) if (rpos[i] == want) r = i;
        if (r < 0) {
            int k2 = -1;
            for (int i = 0; i < 5; i++) if (lpos[i] == want) k2 = i;
            int rr = 0;
            for (int i = 0; i < 5; i++) if (rpos[i] >= 2 && rpos[i] <= 6) { rr = i; break; }
            int tmp = lpos[k2]; lpos[k2] = rpos[rr]; rpos[rr] = tmp;
            S.rest_k[n] = k2; S.rest_r[n] = rr; n++;
            continue;
        }
        int tmp = lpos[k]; lpos[k] = rpos[r]; rpos[r] = tmp;
        S.rest_k[n] = k; S.rest_r[n] = r; n++;
    }
    S.nrest = n;
    for (int i = 0; i < 5; i++) S.fin_rpos[i] = rpos[i];
    // store gather tables: groups of 4 consecutive positions (bits 0,1 vary)
    int rh[3] = {0, 0, 0}; int nh = 0;
    int r0 = 0, r1 = 0;
    for (int i = 0; i < 5; i++) {
        if (rpos[i] == 0) r0 = i;
        else if (rpos[i] == 1) r1 = i;
        else { rh[nh] = i; nh++; }
    }
    for (int g = 0; g < 8; g++) {
        int ph = 0;
        for (int j = 0; j < 3; j++) if ((g >> j) & 1) ph += 1 << rpos[rh[j]];
        S.store_ph[g] = ph;
        for (int j2 = 0; j2 < 4; j2++) {
            int v = 0;
            for (int j = 0; j < 3; j++) if ((g >> j) & 1) v |= 1 << rh[j];
            if (j2 & 1) v |= 1 << r0;
            if (j2 & 2) v |= 1 << r1;
            S.store_v[g][j2] = v;
        }
    }
    return S;
}

constexpr Sched SC = make_sched();          // compile-time (templates / if constexpr)
__constant__ Sched d_S = make_sched();      // runtime copy for the prep kernel

// ============================ Tables ============================
// butterfly: entry[(L*10+t)*256 + e*32 + lane] = (c[pi=2e], s[2e], c[2e+1], s[2e+1])
__device__ float4 g_bt[DEPTH * BDEPTH * 256];
// quintic: qa[(act*512 + e*32 + lane)] = (m0, nb0, m1, nb1) for v=2e,2e+1 ; qs = (sc0, sc1)
__device__ float4 g_qa[(DEPTH - 1) * 512];
__device__ float2 g_qs[(DEPTH - 1) * 512];

// ---------- f32x2 helpers ----------
__device__ __forceinline__ ull pk(float lo, float hi) {
    ull r;
    asm("mov.b64 %0, {%1, %2};" : "=l"(r) : "r"(__float_as_uint(lo)), "r"(__float_as_uint(hi)));
    return r;
}
__device__ __forceinline__ void unpk(ull v, float& lo, float& hi) {
    unsigned a, b;
    asm("mov.b64 {%0, %1}, %2;" : "=r"(a), "=r"(b) : "l"(v));
    lo = __uint_as_float(a);
    hi = __uint_as_float(b);
}
__device__ __forceinline__ ull f2mul(ull a, ull b) {
    ull r;
    asm("mul.rn.f32x2 %0, %1, %2;" : "=l"(r) : "l"(a), "l"(b));
    return r;
}
__device__ __forceinline__ ull f2fma(ull a, ull b, ull c) {
    ull r;
    asm("fma.rn.f32x2 %0, %1, %2, %3;" : "=l"(r) : "l"(a), "l"(b), "l"(c));
    return r;
}
__device__ __forceinline__ void cfence() { asm volatile("" ::: "memory"); }

// ---------- prep ----------
#define BT_ELEMS (DEPTH * BDEPTH * 256)
#define QA_ELEMS ((DEPTH - 1) * 512)

__device__ __forceinline__ float theta_of(const float* bp, int layer, int t, int p0) {
    int j = 0;
#pragma unroll
    for (int k = 0; k < 9; k++) {
        int src = ((k - t) % 10 + 10) % 10;
        j |= ((p0 >> src) & 1) << k;
    }
    return bp[layer * (HALF * BDEPTH) + j * BDEPTH + t];
}

__global__ void prep_all(const float* __restrict__ bp,
                         const float* __restrict__ bias,
                         const float* __restrict__ slope,
                         const float* __restrict__ scale) {
    int e0 = blockIdx.x * blockDim.x + threadIdx.x;
    if (e0 < BT_ELEMS) {
        int T = e0 >> 8;
        int idx = e0 & 255;
        int layer = T / BDEPTH;
        int t = T % BDEPTH;
        int r = d_S.slot[layer][t];
        int M = 1 << r;
        int e = idx >> 5;
        int lane = idx & 31;
        float cs[4];
#pragma unroll
        for (int k = 0; k < 2; k++) {
            int pi = 2 * e + k;
            int v0 = (pi & (M - 1)) | ((pi & ~(M - 1)) << 1);
            int p0 = 0;
            for (int k2 = 0; k2 < 5; k2++) p0 |= ((lane >> k2) & 1) << d_S.lpos[layer][t][k2];
            for (int rr = 0; rr < 5; rr++)
                if (rr != r) p0 |= ((v0 >> rr) & 1) << d_S.rpos[layer][t][rr];
            float th = theta_of(bp, layer, t, p0);
            float s, c;
            sincosf(th, &s, &c);
            cs[2 * k] = c;
            cs[2 * k + 1] = s;
        }
        g_bt[e0] = make_float4(cs[0], cs[1], cs[2], cs[3]);
    } else if (e0 < BT_ELEMS + QA_ELEMS) {
        int q = e0 - BT_ELEMS;
        int act = q >> 9;
        int idx = q & 511;
        int e = idx >> 5;
        int lane = idx & 31;
        float mv[2], nbv[2], scv[2];
#pragma unroll
        for (int k = 0; k < 2; k++) {
            int v = 2 * e + k;
            int p0 = 0;
            for (int k2 = 0; k2 < 5; k2++) p0 |= ((lane >> k2) & 1) << d_S.q_lpos[act][k2];
            for (int rr = 0; rr < 5; rr++) p0 |= ((v >> rr) & 1) << d_S.q_rpos[act][rr];
            float bi = bias[act * WIDTH + p0];
            float sl = slope[act * WIDTH + p0];
            float sc = scale[act * WIDTH + p0];
            mv[k] = sl / sc;
            nbv[k] = -bi / sc;
            scv[k] = sc;
        }
        g_qa[q] = make_float4(mv[0], nbv[0], mv[1], nbv[1]);
        g_qs[q] = make_float2(scv[0], scv[1]);
    }
}

// ---------- main kernel building blocks ----------

template <int R>
__device__ __forceinline__ void reg_bfly(ull (&val)[64], int lane, const float4* __restrict__ bt) {
    constexpr int M = 1 << R;
#pragma unroll
    for (int e = 0; e < 8; e++) {
        float4 q = __ldg(bt + e * 32 + lane);
#pragma unroll
        for (int k = 0; k < 2; k++) {
            const int pi = 2 * e + k;
            const int v0 = (pi & (M - 1)) | ((pi & ~(M - 1)) << 1);
            const int v1 = v0 | M;
            float c = k ? q.z : q.x;
            float s = k ? q.w : q.y;
            ull c2 = pk(c, c);
            ull s2 = pk(s, s);
            ull ns2 = s2 ^ 0x8000000080000000ULL;
#pragma unroll
            for (int h = 0; h < 2; h++) {
                ull x0 = val[v0 * 2 + h];
                ull x1 = val[v1 * 2 + h];
                val[v0 * 2 + h] = f2fma(c2, x0, f2mul(s2, x1));   // c*x0 + s*x1
                val[v1 * 2 + h] = f2fma(c2, x1, f2mul(ns2, x0));  // c*x1 - s*x0
            }
        }
        if ((e & 3) == 3) cfence();
    }
}

// Anti-diagonal exchange: swaps roles of lane bit K and reg slot R.
// Thread with lane-bit==0 sends val[v1], receives partner's val[v0] (and vice versa).
// NO fences: all 32 shfl are independent and must pipeline (26-cyc shfl latency).
template <int K, int R>
__device__ __forceinline__ void swap_lr(ull (&val)[64], int lane) {
    constexpr int LM = 1 << K;
    constexpr int M = 1 << R;
    const bool a = (lane & LM) != 0;
#pragma unroll
    for (int pi = 0; pi < 16; pi++) {
        const int v0 = (pi & (M - 1)) | ((pi & ~(M - 1)) << 1);
        const int v1 = v0 | M;
#pragma unroll
        for (int h = 0; h < 2; h++) {
            ull send = a ? val[v0 * 2 + h] : val[v1 * 2 + h];
            ull recv = __shfl_xor_sync(0xffffffffu, send, LM);
            if (a) val[v0 * 2 + h] = recv;
            else   val[v1 * 2 + h] = recv;
        }
    }
}

template <int L, int T>
__device__ __forceinline__ void step(ull (&val)[64], int lane) {
    constexpr int R = SC.slot[L][T];
    constexpr int K = SC.swpl[L][T];
    if constexpr (K >= 0) swap_lr<K, R>(val, lane);
    reg_bfly<R>(val, lane, g_bt + (L * BDEPTH + T) * 256);
}

__device__ __forceinline__ void do_quintic(ull (&val)[64], int lane, int act) {
    const float4* __restrict__ qa = g_qa + act * 512;
    const float2* __restrict__ qs = g_qs + act * 512;
    const ull C1875 = 0x3FF000003FF00000ULL;  // (1.875, 1.875)
    const ull CM125 = 0xBFA00000BFA00000ULL;  // (-1.25, -1.25)
    const ull C0375 = 0x3EC000003EC00000ULL;  // (0.375, 0.375)
#pragma unroll
    for (int e = 0; e < 16; e++) {
        float4 q = __ldg(qa + e * 32 + lane);
        float2 sq = __ldg(qs + e * 32 + lane);
#pragma unroll
        for (int k = 0; k < 2; k++) {
            const int v = 2 * e + k;
            ull m2 = pk(k ? q.z : q.x, k ? q.z : q.x);
            ull nb2 = pk(k ? q.w : q.y, k ? q.w : q.y);
            ull sc2 = pk(k ? sq.y : sq.x, k ? sq.y : sq.x);
#pragma unroll
            for (int h = 0; h < 2; h++) {
                ull u = f2fma(val[v * 2 + h], m2, nb2);
                float lo, hi;
                unpk(u, lo, hi);
                lo = fminf(fmaxf(lo, -1.0f), 1.0f);
                hi = fminf(fmaxf(hi, -1.0f), 1.0f);
                u = pk(lo, hi);
                ull u2 = f2mul(u, u);
                ull p = f2fma(u2, C0375, CM125);
                p = f2fma(u2, p, C1875);
                val[v * 2 + h] = f2mul(f2mul(u, p), sc2);
            }
        }
        if ((e & 3) == 3) cfence();
    }
}

template <int L>
__device__ __forceinline__ void run_layer(ull (&val)[64], int lane) {
    step<L, 0>(val, lane);
    step<L, 1>(val, lane);
    step<L, 2>(val, lane);
    step<L, 3>(val, lane);
    step<L, 4>(val, lane);
    step<L, 5>(val, lane);
    step<L, 6>(val, lane);
    step<L, 7>(val, lane);
    step<L, 8>(val, lane);
    step<L, 9>(val, lane);
    if constexpr (L < DEPTH - 1) do_quintic(val, lane, L);
}

template <int I>
__device__ __forceinline__ void restore_all(ull (&val)[64], int lane) {
    if constexpr (I < 12) {
        if constexpr (I < SC.nrest) {
            swap_lr<SC.rest_k[I], SC.rest_r[I]>(val, lane);
            restore_all<I + 1>(val, lane);
        }
    }
}

template <int G>
__device__ __forceinline__ void store_groups(ull (&val)[64], int lane,
                                             float* __restrict__ yr0, float* __restrict__ yr1,
                                             float* __restrict__ yr2, float* __restrict__ yr3) {
    if constexpr (G < 8) {
        constexpr int ph = SC.store_ph[G];
        constexpr int w0 = SC.store_v[G][0];
        constexpr int w1 = SC.store_v[G][1];
        constexpr int w2 = SC.store_v[G][2];
        constexpr int w3 = SC.store_v[G][3];
        const int off = ph + lane * 4;
        {
            float4 a, b;
            unpk(val[w0 * 2 + 0], a.x, b.x);
            unpk(val[w1 * 2 + 0], a.y, b.y);
            unpk(val[w2 * 2 + 0], a.z, b.z);
            unpk(val[w3 * 2 + 0], a.w, b.w);
            *(float4*)(yr0 + off) = a;
            *(float4*)(yr1 + off) = b;
        }
        cfence();
        {
            float4 c, d;
            unpk(val[w0 * 2 + 1], c.x, d.x);
            unpk(val[w1 * 2 + 1], c.y, d.y);
            unpk(val[w2 * 2 + 1], c.z, d.z);
            unpk(val[w3 * 2 + 1], c.w, d.w);
            *(float4*)(yr2 + off) = c;
            *(float4*)(yr3 + off) = d;
        }
        cfence();
        store_groups<G + 1>(val, lane, yr0, yr1, yr2, yr3);
    }
}

__global__ void __launch_bounds__(128)
net_kernel(const float* __restrict__ X, float* __restrict__ Y) {
    const int lane = threadIdx.x & 31;
    const int w = blockIdx.x * 4 + (threadIdx.x >> 5);
    const long long row0 = (long long)w * 4;
    const float* __restrict__ xr0 = X + row0 * WIDTH;
    const float* __restrict__ xr1 = xr0 + WIDTH;
    const float* __restrict__ xr2 = xr1 + WIDTH;
    const float* __restrict__ xr3 = xr2 + WIDTH;

    ull val[64];

    // load (initial mapping: v = vhi*4 + j <-> p = vhi*128 + lane*4 + j)
#pragma unroll
    for (int vhi = 0; vhi < 8; vhi++) {
        int off = vhi * 128 + lane * 4;
        int s = vhi * 4;
        {
            float4 a = *(const float4*)(xr0 + off);
            float4 b = *(const float4*)(xr1 + off);
            val[(s + 0) * 2 + 0] = pk(a.x, b.x);
            val[(s + 1) * 2 + 0] = pk(a.y, b.y);
            val[(s + 2) * 2 + 0] = pk(a.z, b.z);
            val[(s + 3) * 2 + 0] = pk(a.w, b.w);
        }
        cfence();
        {
            float4 c = *(const float4*)(xr2 + off);
            float4 d = *(const float4*)(xr3 + off);
            val[(s + 0) * 2 + 1] = pk(c.x, d.x);
            val[(s + 1) * 2 + 1] = pk(c.y, d.y);
            val[(s + 2) * 2 + 1] = pk(c.z, d.z);
            val[(s + 3) * 2 + 1] = pk(c.w, d.w);
        }
        cfence();
    }

    run_layer<0>(val, lane);
    run_layer<1>(val, lane);
    run_layer<2>(val, lane);
    run_layer<3>(val, lane);
    run_layer<4>(val, lane);
    run_layer<5>(val, lane);
    run_layer<6>(val, lane);
    run_layer<7>(val, lane);

    restore_all<0>(val, lane);

    float* __restrict__ yr0 = Y + row0 * WIDTH;
    float* __restrict__ yr1 = yr0 + WIDTH;
    float* __restrict__ yr2 = yr1 + WIDTH;
    float* __restrict__ yr3 = yr2 + WIDTH;
    store_groups<0>(val, lane, yr0, yr1, yr2, yr3);
}

extern "C" void kernel_launch(void* const* d_in, const int* in_sizes, int n_in,
                              void* d_out, int out_size) {
    const float* X     = (const float*)d_in[0];
    const float* bp    = (const float*)d_in[1];
    const float* bias  = (const float*)d_in[2];
    const float* slope = (const float*)d_in[3];
    const float* scale = (const float*)d_in[4];
    float* Y = (float*)d_out;

    prep_all<<<(BT_ELEMS + QA_ELEMS + QA_ELEMS + 255) / 256, 256>>>(bp, bias, slope, scale);
    // 4 rows/warp, 4 warps/CTA; 2 CTAs/SM (regfile-optimal point)
    net_kernel<<<BATCH / 16, 128>>>(X, Y);
}

// round 12
// speedup vs baseline: 1.9421x; 1.9421x over previous
#include <cuda_runtime.h>
#include <cstdint>

#define WIDTH  1024
#define HALF   512
#define DEPTH  8
#define BDEPTH 10
#define BATCH  65536

typedef unsigned long long ull;

// Geometry (R8 champion):
//   lane = p bits [6:2]  (32 lanes)
//   slot v (0..31): p = ((v>>2)<<7) | (lane<<2) | (v&3)   -> v bits = p bits {1,0,9,8,7}
//   thread holds val[v*2+h]: h=0 rows(0,1), h=1 rows(2,3) packed in f32x2.
// Steps t (bit b = 9-t): t=0,1,2 reg (v bits 4,3,2); t=3..7 lane (lane bits 4..0);
//                        t=8,9 reg (v bits 1,0).
//
// g_bt (steps t=1..9): 256 float4 per step, LDG.128:
//   reg step:  entry[e*32 + lane], e=0..7:  (c[pi=2e], s[2e], c[2e+1], s[2e+1])
//   lane step: entry[e*16 + lp],  e=0..15: (c[v=2e],  s[2e], c[2e+1], s[2e+1])
// g_t0 (step t=0, scale-folded): entry[L*512 + pi*32 + lane] = (a, b, -g, d)
//   n0 = a*x0 + b*x1 ; n1 = (-g)*x0 + d*x1 with a=c*sc0, b=s*sc1, g=s*sc0, d=c*sc1
//   (sc = previous layer's quintic scale; sc=1 for layer 0).
__device__ float4 g_bt[DEPTH * BDEPTH * 256];
__device__ float4 g_t0[DEPTH * 512];
// quintic (scale folded out): entry[act*512 + e*32 + lane] = (m_v0, nb_v0, m_v1, nb_v1)
__device__ float4 g_qt[(DEPTH - 1) * 512];

// ---------- f32x2 helpers ----------
__device__ __forceinline__ ull pk(float lo, float hi) {
    ull r;
    asm("mov.b64 %0, {%1, %2};" : "=l"(r) : "r"(__float_as_uint(lo)), "r"(__float_as_uint(hi)));
    return r;
}
__device__ __forceinline__ void unpk(ull v, float& lo, float& hi) {
    unsigned a, b;
    asm("mov.b64 {%0, %1}, %2;" : "=r"(a), "=r"(b) : "l"(v));
    lo = __uint_as_float(a);
    hi = __uint_as_float(b);
}
__device__ __forceinline__ ull f2mul(ull a, ull b) {
    ull r;
    asm("mul.rn.f32x2 %0, %1, %2;" : "=l"(r) : "l"(a), "l"(b));
    return r;
}
__device__ __forceinline__ ull f2fma(ull a, ull b, ull c) {
    ull r;
    asm("fma.rn.f32x2 %0, %1, %2, %3;" : "=l"(r) : "l"(a), "l"(b), "l"(c));
    return r;
}
__device__ __forceinline__ void cfence() { asm volatile("" ::: "memory"); }

// ---------- prep ----------
#define BT_ELEMS (DEPTH * BDEPTH * 256)
#define T0_ELEMS (DEPTH * 512)
#define QT_ELEMS ((DEPTH - 1) * 512)

__device__ __forceinline__ float theta_of(const float* bp, int layer, int t, int p0) {
    int j = 0;
#pragma unroll
    for (int k = 0; k < 9; k++) {
        int src = ((k - t) % 10 + 10) % 10;
        j |= ((p0 >> src) & 1) << k;
    }
    return bp[layer * (HALF * BDEPTH) + j * BDEPTH + t];
}

__global__ void prep_all(const float* __restrict__ bp,
                         const float* __restrict__ bias,
                         const float* __restrict__ slope,
                         const float* __restrict__ scale) {
    int e0 = blockIdx.x * blockDim.x + threadIdx.x;
    if (e0 < BT_ELEMS) {
        int T = e0 >> 8;
        int idx = e0 & 255;
        int layer = T / BDEPTH;
        int t = T % BDEPTH;
        if (t == 0) return;  // t=0 handled via g_t0
        int b = 9 - t;

        float4 out;
        if (b >= 7 || b <= 1) {
            int sbit = (b >= 7) ? (b - 5) : b;
            int m = 1 << sbit;
            int e = idx >> 5;
            int lane = idx & 31;
            float cs[4];
#pragma unroll
            for (int k = 0; k < 2; k++) {
                int pi = 2 * e + k;
                int v0 = (pi & (m - 1)) | ((pi & ~(m - 1)) << 1);
                int p0 = ((v0 >> 2) << 7) | (lane << 2) | (v0 & 3);
                float th = theta_of(bp, layer, t, p0);
                float s, c;
                sincosf(th, &s, &c);
                cs[2 * k] = c;
                cs[2 * k + 1] = s;
            }
            out = make_float4(cs[0], cs[1], cs[2], cs[3]);
        } else {
            int lm = 1 << (b - 2);
            int e = idx >> 4;
            int lp = idx & 15;
            int l0 = (lp & (lm - 1)) | ((lp & ~(lm - 1)) << 1);
            float cs[4];
#pragma unroll
            for (int k = 0; k < 2; k++) {
                int v = 2 * e + k;
                int p0 = ((v >> 2) << 7) | (l0 << 2) | (v & 3);
                float th = theta_of(bp, layer, t, p0);
                float s, c;
                sincosf(th, &s, &c);
                cs[2 * k] = c;
                cs[2 * k + 1] = s;
            }
            out = make_float4(cs[0], cs[1], cs[2], cs[3]);
        }
        g_bt[e0] = out;
    } else if (e0 < BT_ELEMS + T0_ELEMS) {
        int q = e0 - BT_ELEMS;
        int layer = q >> 9;
        int idx = q & 511;
        int pi = idx >> 5;          // pair 0..15: v0 = pi, v1 = pi|16 (M=16)
        int lane = idx & 31;
        int v0 = pi, v1 = pi | 16;
        int p0 = ((v0 >> 2) << 7) | (lane << 2) | (v0 & 3);
        int p1 = ((v1 >> 2) << 7) | (lane << 2) | (v1 & 3);
        float th = theta_of(bp, layer, 0, p0);
        float s, c;
        sincosf(th, &s, &c);
        float sc0 = 1.0f, sc1 = 1.0f;
        if (layer > 0) {
            sc0 = scale[(layer - 1) * WIDTH + p0];
            sc1 = scale[(layer - 1) * WIDTH + p1];
        }
        g_t0[q] = make_float4(c * sc0, s * sc1, -s * sc0, c * sc1);
    } else if (e0 < BT_ELEMS + T0_ELEMS + QT_ELEMS) {
        int q = e0 - BT_ELEMS - T0_ELEMS;
        int act = q >> 9;
        int idx = q & 511;
        int e = idx >> 5;           // v0 = 2e, v1 = 2e+1
        int l = idx & 31;
        float mv[2], nbv[2];
#pragma unroll
        for (int k = 0; k < 2; k++) {
            int v = 2 * e + k;
            int p0 = ((v >> 2) << 7) | (l << 2) | (v & 3);
            float bi = bias[act * WIDTH + p0];
            float sl = slope[act * WIDTH + p0];
            float sc = scale[act * WIDTH + p0];
            mv[k] = sl / sc;
            nbv[k] = -bi / sc;
        }
        g_qt[q] = make_float4(mv[0], nbv[0], mv[1], nbv[1]);
    }
}

// ---------- main kernel ----------

__device__ __forceinline__ void bfly_pair(ull (&val)[64], int v0, int v1, float c, float s) {
    ull c2 = pk(c, c);
    ull s2 = pk(s, s);
    ull ns2 = s2 ^ 0x8000000080000000ULL;
#pragma unroll
    for (int h = 0; h < 2; h++) {
        ull x0 = val[v0 * 2 + h];
        ull x1 = val[v1 * 2 + h];
        val[v0 * 2 + h] = f2fma(c2, x0, f2mul(s2, x1));   // n0 =  c*x0 + s*x1
        val[v1 * 2 + h] = f2fma(c2, x1, f2mul(ns2, x0));  // n1 =  c*x1 - s*x0
    }
}

// t=0 with folded scale: n0 = a*x0 + b*x1 ; n1 = g*x0 + d*x1 (g pre-negated)
__device__ __forceinline__ void t0_step(ull (&val)[64], int lane, const float4* __restrict__ t0t) {
#pragma unroll
    for (int pi = 0; pi < 16; pi++) {
        float4 q = __ldg(t0t + pi * 32 + lane);
        ull a2 = pk(q.x, q.x);
        ull b2 = pk(q.y, q.y);
        ull g2 = pk(q.z, q.z);
        ull d2 = pk(q.w, q.w);
        const int v0 = pi, v1 = pi | 16;
#pragma unroll
        for (int h = 0; h < 2; h++) {
            ull x0 = val[v0 * 2 + h];
            ull x1 = val[v1 * 2 + h];
            val[v0 * 2 + h] = f2fma(a2, x0, f2mul(b2, x1));
            val[v1 * 2 + h] = f2fma(g2, x0, f2mul(d2, x1));
        }
        if ((pi & 3) == 3) cfence();
    }
}

template <int M>
__device__ __forceinline__ void reg_step(ull (&val)[64], int lane, const float4* __restrict__ bt) {
#pragma unroll
    for (int e = 0; e < 8; e++) {
        float4 q = __ldg(bt + e * 32 + lane);
        {
            const int pi = 2 * e;
            const int v0 = (pi & (M - 1)) | ((pi & ~(M - 1)) << 1);
            bfly_pair(val, v0, v0 | M, q.x, q.y);
        }
        {
            const int pi = 2 * e + 1;
            const int v0 = (pi & (M - 1)) | ((pi & ~(M - 1)) << 1);
            bfly_pair(val, v0, v0 | M, q.z, q.w);
        }
        if ((e & 3) == 3) cfence();
    }
}

// Lane butterfly. All 4 shuffles per table fetch are issued BEFORE any butterfly
// consumes them, giving each shfl guaranteed slack and letting ptxas interleave
// the previous quartet's FMAs under the next quartet's shfl latency.
template <int LM>
__device__ __forceinline__ void lane_step(ull (&val)[64], int lane, const float4* __restrict__ bt) {
    const ull smask = (lane & LM) ? 0x8000000080000000ULL : 0ULL;
    const int lp = (lane & (LM - 1)) | ((lane >> 1) & ~(LM - 1));
#pragma unroll
    for (int e = 0; e < 16; e++) {
        float4 q = __ldg(bt + e * 16 + lp);
        const int va = 2 * e;
        const int vb = 2 * e + 1;
        // issue all 4 partner shuffles up front
        ull xa0 = val[va * 2 + 0];
        ull xa1 = val[va * 2 + 1];
        ull xb0 = val[vb * 2 + 0];
        ull xb1 = val[vb * 2 + 1];
        ull pa0 = __shfl_xor_sync(0xffffffffu, xa0, LM);
        ull pa1 = __shfl_xor_sync(0xffffffffu, xa1, LM);
        ull pb0 = __shfl_xor_sync(0xffffffffu, xb0, LM);
        ull pb1 = __shfl_xor_sync(0xffffffffu, xb1, LM);
        // butterflies
        ull ca = pk(q.x, q.x);
        ull sa = pk(q.y, q.y) ^ smask;
        ull cb = pk(q.z, q.z);
        ull sb = pk(q.w, q.w) ^ smask;
        val[va * 2 + 0] = f2fma(ca, xa0, f2mul(sa, pa0));
        val[va * 2 + 1] = f2fma(ca, xa1, f2mul(sa, pa1));
        val[vb * 2 + 0] = f2fma(cb, xb0, f2mul(sb, pb0));
        val[vb * 2 + 1] = f2fma(cb, xb1, f2mul(sb, pb1));
        if ((e & 3) == 3) cfence();
    }
}

// quintic WITHOUT trailing scale (folded into next layer's t0)
__device__ __forceinline__ void quintic(ull (&val)[64], int lane, int act) {
    const float4* __restrict__ qt = g_qt + act * 512;
    const ull C1875 = 0x3FF000003FF00000ULL;  // (1.875, 1.875)
    const ull CM125 = 0xBFA00000BFA00000ULL;  // (-1.25, -1.25)
    const ull C0375 = 0x3EC000003EC00000ULL;  // (0.375, 0.375)
#pragma unroll
    for (int e = 0; e < 16; e++) {
        float4 q = __ldg(qt + e * 32 + lane);
#pragma unroll
        for (int k = 0; k < 2; k++) {
            const int v = 2 * e + k;
            ull m2 = pk(k ? q.z : q.x, k ? q.z : q.x);
            ull nb2 = pk(k ? q.w : q.y, k ? q.w : q.y);
#pragma unroll
            for (int h = 0; h < 2; h++) {
                ull u = f2fma(val[v * 2 + h], m2, nb2);
                float lo, hi;
                unpk(u, lo, hi);
                lo = fminf(fmaxf(lo, -1.0f), 1.0f);
                hi = fminf(fmaxf(hi, -1.0f), 1.0f);
                u = pk(lo, hi);
                ull u2 = f2mul(u, u);
                ull p = f2fma(u2, C0375, CM125);
                p = f2fma(u2, p, C1875);
                val[v * 2 + h] = f2mul(u, p);
            }
        }
        if ((e & 3) == 3) cfence();
    }
}

__global__ void __launch_bounds__(128)
net_kernel(const float* __restrict__ X, float* __restrict__ Y) {
    const int lane = threadIdx.x & 31;
    const int w = blockIdx.x * 4 + (threadIdx.x >> 5);
    const long long row0 = (long long)w * 4;
    const float* __restrict__ xr0 = X + row0 * WIDTH;
    const float* __restrict__ xr1 = xr0 + WIDTH;
    const float* __restrict__ xr2 = xr1 + WIDTH;
    const float* __restrict__ xr3 = xr2 + WIDTH;

    ull val[64];

    // load: 4 rows; val[v*2+h]: h=0 -> (row0,row1), h=1 -> (row2,row3)
#pragma unroll
    for (int vhi = 0; vhi < 8; vhi++) {
        int off = vhi * 128 + lane * 4;
        int s = vhi * 4;
        {
            float4 a = *(const float4*)(xr0 + off);
            float4 b = *(const float4*)(xr1 + off);
            val[(s + 0) * 2 + 0] = pk(a.x, b.x);
            val[(s + 1) * 2 + 0] = pk(a.y, b.y);
            val[(s + 2) * 2 + 0] = pk(a.z, b.z);
            val[(s + 3) * 2 + 0] = pk(a.w, b.w);
        }
        cfence();
        {
            float4 c = *(const float4*)(xr2 + off);
            float4 d = *(const float4*)(xr3 + off);
            val[(s + 0) * 2 + 1] = pk(c.x, d.x);
            val[(s + 1) * 2 + 1] = pk(c.y, d.y);
            val[(s + 2) * 2 + 1] = pk(c.z, d.z);
            val[(s + 3) * 2 + 1] = pk(c.w, d.w);
        }
        cfence();
    }

#pragma unroll 1
    for (int layer = 0; layer < DEPTH; layer++) {
        const float4* __restrict__ bt = g_bt + layer * (BDEPTH * 256);
        t0_step(val, lane, g_t0 + layer * 512);  // t=0: p bit 9, scale-folded
        reg_step<8>(val, lane, bt + 1 * 256);    // t=1: p bit 8 (v bit 3)
        reg_step<4>(val, lane, bt + 2 * 256);    // t=2: p bit 7 (v bit 2)
        lane_step<16>(val, lane, bt + 3 * 256);  // t=3: p bit 6 (lane bit 4)
        lane_step<8>(val, lane, bt + 4 * 256);   // t=4: p bit 5
        lane_step<4>(val, lane, bt + 5 * 256);   // t=5: p bit 4
        lane_step<2>(val, lane, bt + 6 * 256);   // t=6: p bit 3
        lane_step<1>(val, lane, bt + 7 * 256);   // t=7: p bit 2 (lane bit 0)
        reg_step<2>(val, lane, bt + 8 * 256);    // t=8: p bit 1 (v bit 1)
        reg_step<1>(val, lane, bt + 9 * 256);    // t=9: p bit 0 (v bit 0)
        if (layer < DEPTH - 1) quintic(val, lane, layer);
    }

    // store (net permutation over 10 steps per layer is identity)
    float* __restrict__ yr0 = Y + row0 * WIDTH;
    float* __restrict__ yr1 = yr0 + WIDTH;
    float* __restrict__ yr2 = yr1 + WIDTH;
    float* __restrict__ yr3 = yr2 + WIDTH;
#pragma unroll
    for (int vhi = 0; vhi < 8; vhi++) {
        int off = vhi * 128 + lane * 4;
        int s = vhi * 4;
        {
            float4 a, b;
            unpk(val[(s + 0) * 2 + 0], a.x, b.x);
            unpk(val[(s + 1) * 2 + 0], a.y, b.y);
            unpk(val[(s + 2) * 2 + 0], a.z, b.z);
            unpk(val[(s + 3) * 2 + 0], a.w, b.w);
            *(float4*)(yr0 + off) = a;
            *(float4*)(yr1 + off) = b;
        }
        cfence();
        {
            float4 c, d;
            unpk(val[(s + 0) * 2 + 1], c.x, d.x);
            unpk(val[(s + 1) * 2 + 1], c.y, d.y);
            unpk(val[(s + 2) * 2 + 1], c.z, d.z);
            unpk(val[(s + 3) * 2 + 1], c.w, d.w);
            *(float4*)(yr2 + off) = c;
            *(float4*)(yr3 + off) = d;
        }
        cfence();
    }
}

extern "C" void kernel_launch(void* const* d_in, const int* in_sizes, int n_in,
                              void* d_out, int out_size) {
    const float* X     = (const float*)d_in[0];
    const float* bp    = (const float*)d_in[1];
    const float* bias  = (const float*)d_in[2];
    const float* slope = (const float*)d_in[3];
    const float* scale = (const float*)d_in[4];
    float* Y = (float*)d_out;

    prep_all<<<(BT_ELEMS + T0_ELEMS + QT_ELEMS + 255) / 256, 256>>>(bp, bias, slope, scale);
    // 4 rows/warp, 4 warps/CTA -> 16 rows per CTA; ~252 regs, 2 CTAs/SM
    net_kernel<<<BATCH / 16, 128>>>(X, Y);
}

// round 13
// speedup vs baseline: 1.9502x; 1.0042x over previous
#include <cuda_runtime.h>
#include <cstdint>

#define WIDTH  1024
#define HALF   512
#define DEPTH  8
#define BDEPTH 10
#define BATCH  65536

typedef unsigned long long ull;

// Geometry (R8 champion):
//   lane = p bits [6:2]  (32 lanes)
//   slot v (0..31): p = ((v>>2)<<7) | (lane<<2) | (v&3)   -> v bits = p bits {1,0,9,8,7}
//   thread holds val[v*2+h]: h=0 rows(0,1), h=1 rows(2,3) packed in f32x2.
// Steps t (bit b = 9-t): t=0,1,2 reg (v bits 4,3,2); t=3..7 lane (lane bits 4..0);
//                        t=8,9 reg (v bits 1,0).
//
// g_bt (steps t=1..9): 256 float4 per step, LDG.128:
//   reg step:  entry[e*32 + lane], e=0..7:  (c[pi=2e], s[2e], c[2e+1], s[2e+1])
//   lane step: entry[e*16 + lp],  e=0..15: (c[v=2e],  s[2e], c[2e+1], s[2e+1])
// g_t0 (step t=0, scale-folded): entry[L*512 + pi*32 + lane] = (a, b, -g, d)
//   n0 = a*x0 + b*x1 ; n1 = (-g)*x0 + d*x1 with a=c*sc0, b=s*sc1, g=s*sc0, d=c*sc1
//   (sc = previous layer's quintic scale; sc=1 for layer 0).
__device__ float4 g_bt[DEPTH * BDEPTH * 256];
__device__ float4 g_t0[DEPTH * 512];
// quintic (scale folded out): entry[act*512 + e*32 + lane] = (m_v0, nb_v0, m_v1, nb_v1)
__device__ float4 g_qt[(DEPTH - 1) * 512];

// ---------- f32x2 helpers ----------
__device__ __forceinline__ ull pk(float lo, float hi) {
    ull r;
    asm("mov.b64 %0, {%1, %2};" : "=l"(r) : "r"(__float_as_uint(lo)), "r"(__float_as_uint(hi)));
    return r;
}
__device__ __forceinline__ void unpk(ull v, float& lo, float& hi) {
    unsigned a, b;
    asm("mov.b64 {%0, %1}, %2;" : "=r"(a), "=r"(b) : "l"(v));
    lo = __uint_as_float(a);
    hi = __uint_as_float(b);
}
__device__ __forceinline__ ull f2mul(ull a, ull b) {
    ull r;
    asm("mul.rn.f32x2 %0, %1, %2;" : "=l"(r) : "l"(a), "l"(b));
    return r;
}
__device__ __forceinline__ ull f2fma(ull a, ull b, ull c) {
    ull r;
    asm("fma.rn.f32x2 %0, %1, %2, %3;" : "=l"(r) : "l"(a), "l"(b), "l"(c));
    return r;
}
__device__ __forceinline__ void cfence() { asm volatile("" ::: "memory"); }

// ---------- prep ----------
#define BT_ELEMS (DEPTH * BDEPTH * 256)
#define T0_ELEMS (DEPTH * 512)
#define QT_ELEMS ((DEPTH - 1) * 512)

__device__ __forceinline__ float theta_of(const float* bp, int layer, int t, int p0) {
    int j = 0;
#pragma unroll
    for (int k = 0; k < 9; k++) {
        int src = ((k - t) % 10 + 10) % 10;
        j |= ((p0 >> src) & 1) << k;
    }
    return bp[layer * (HALF * BDEPTH) + j * BDEPTH + t];
}

__global__ void prep_all(const float* __restrict__ bp,
                         const float* __restrict__ bias,
                         const float* __restrict__ slope,
                         const float* __restrict__ scale) {
    int e0 = blockIdx.x * blockDim.x + threadIdx.x;
    if (e0 < BT_ELEMS) {
        int T = e0 >> 8;
        int idx = e0 & 255;
        int layer = T / BDEPTH;
        int t = T % BDEPTH;
        if (t == 0) return;  // t=0 handled via g_t0
        int b = 9 - t;

        float4 out;
        if (b >= 7 || b <= 1) {
            int sbit = (b >= 7) ? (b - 5) : b;
            int m = 1 << sbit;
            int e = idx >> 5;
            int lane = idx & 31;
            float cs[4];
#pragma unroll
            for (int k = 0; k < 2; k++) {
                int pi = 2 * e + k;
                int v0 = (pi & (m - 1)) | ((pi & ~(m - 1)) << 1);
                int p0 = ((v0 >> 2) << 7) | (lane << 2) | (v0 & 3);
                float th = theta_of(bp, layer, t, p0);
                float s, c;
                sincosf(th, &s, &c);
                cs[2 * k] = c;
                cs[2 * k + 1] = s;
            }
            out = make_float4(cs[0], cs[1], cs[2], cs[3]);
        } else {
            int lm = 1 << (b - 2);
            int e = idx >> 4;
            int lp = idx & 15;
            int l0 = (lp & (lm - 1)) | ((lp & ~(lm - 1)) << 1);
            float cs[4];
#pragma unroll
            for (int k = 0; k < 2; k++) {
                int v = 2 * e + k;
                int p0 = ((v >> 2) << 7) | (l0 << 2) | (v & 3);
                float th = theta_of(bp, layer, t, p0);
                float s, c;
                sincosf(th, &s, &c);
                cs[2 * k] = c;
                cs[2 * k + 1] = s;
            }
            out = make_float4(cs[0], cs[1], cs[2], cs[3]);
        }
        g_bt[e0] = out;
    } else if (e0 < BT_ELEMS + T0_ELEMS) {
        int q = e0 - BT_ELEMS;
        int layer = q >> 9;
        int idx = q & 511;
        int pi = idx >> 5;          // pair 0..15: v0 = pi, v1 = pi|16 (M=16)
        int lane = idx & 31;
        int v0 = pi, v1 = pi | 16;
        int p0 = ((v0 >> 2) << 7) | (lane << 2) | (v0 & 3);
        int p1 = ((v1 >> 2) << 7) | (lane << 2) | (v1 & 3);
        float th = theta_of(bp, layer, 0, p0);
        float s, c;
        sincosf(th, &s, &c);
        float sc0 = 1.0f, sc1 = 1.0f;
        if (layer > 0) {
            sc0 = scale[(layer - 1) * WIDTH + p0];
            sc1 = scale[(layer - 1) * WIDTH + p1];
        }
        g_t0[q] = make_float4(c * sc0, s * sc1, -s * sc0, c * sc1);
    } else if (e0 < BT_ELEMS + T0_ELEMS + QT_ELEMS) {
        int q = e0 - BT_ELEMS - T0_ELEMS;
        int act = q >> 9;
        int idx = q & 511;
        int e = idx >> 5;           // v0 = 2e, v1 = 2e+1
        int l = idx & 31;
        float mv[2], nbv[2];
#pragma unroll
        for (int k = 0; k < 2; k++) {
            int v = 2 * e + k;
            int p0 = ((v >> 2) << 7) | (l << 2) | (v & 3);
            float bi = bias[act * WIDTH + p0];
            float sl = slope[act * WIDTH + p0];
            float sc = scale[act * WIDTH + p0];
            mv[k] = sl / sc;
            nbv[k] = -bi / sc;
        }
        g_qt[q] = make_float4(mv[0], nbv[0], mv[1], nbv[1]);
    }
}

// ---------- main kernel ----------

__device__ __forceinline__ void bfly_pair(ull (&val)[64], int v0, int v1, float c, float s) {
    ull c2 = pk(c, c);
    ull s2 = pk(s, s);
    ull ns2 = s2 ^ 0x8000000080000000ULL;
#pragma unroll
    for (int h = 0; h < 2; h++) {
        ull x0 = val[v0 * 2 + h];
        ull x1 = val[v1 * 2 + h];
        val[v0 * 2 + h] = f2fma(c2, x0, f2mul(s2, x1));   // n0 =  c*x0 + s*x1
        val[v1 * 2 + h] = f2fma(c2, x1, f2mul(ns2, x0));  // n1 =  c*x1 - s*x0
    }
}

// t=0 with folded scale: n0 = a*x0 + b*x1 ; n1 = g*x0 + d*x1 (g pre-negated)
__device__ __forceinline__ void t0_step(ull (&val)[64], int lane, const float4* __restrict__ t0t) {
#pragma unroll
    for (int pi = 0; pi < 16; pi++) {
        float4 q = __ldg(t0t + pi * 32 + lane);
        ull a2 = pk(q.x, q.x);
        ull b2 = pk(q.y, q.y);
        ull g2 = pk(q.z, q.z);
        ull d2 = pk(q.w, q.w);
        const int v0 = pi, v1 = pi | 16;
#pragma unroll
        for (int h = 0; h < 2; h++) {
            ull x0 = val[v0 * 2 + h];
            ull x1 = val[v1 * 2 + h];
            val[v0 * 2 + h] = f2fma(a2, x0, f2mul(b2, x1));
            val[v1 * 2 + h] = f2fma(g2, x0, f2mul(d2, x1));
        }
        if ((pi & 3) == 3) cfence();
    }
}

template <int M>
__device__ __forceinline__ void reg_step(ull (&val)[64], int lane, const float4* __restrict__ bt) {
#pragma unroll
    for (int e = 0; e < 8; e++) {
        float4 q = __ldg(bt + e * 32 + lane);
        {
            const int pi = 2 * e;
            const int v0 = (pi & (M - 1)) | ((pi & ~(M - 1)) << 1);
            bfly_pair(val, v0, v0 | M, q.x, q.y);
        }
        {
            const int pi = 2 * e + 1;
            const int v0 = (pi & (M - 1)) | ((pi & ~(M - 1)) << 1);
            bfly_pair(val, v0, v0 | M, q.z, q.w);
        }
        if ((e & 3) == 3) cfence();
    }
}

// Lane butterfly. All 4 shuffles per table fetch are issued BEFORE any butterfly
// consumes them, giving each shfl guaranteed slack and letting ptxas interleave
// the previous quartet's FMAs under the next quartet's shfl latency.
template <int LM>
__device__ __forceinline__ void lane_step(ull (&val)[64], int lane, const float4* __restrict__ bt) {
    const ull smask = (lane & LM) ? 0x8000000080000000ULL : 0ULL;
    const int lp = (lane & (LM - 1)) | ((lane >> 1) & ~(LM - 1));
#pragma unroll
    for (int e = 0; e < 16; e++) {
        float4 q = __ldg(bt + e * 16 + lp);
        const int va = 2 * e;
        const int vb = 2 * e + 1;
        // issue all 4 partner shuffles up front
        ull xa0 = val[va * 2 + 0];
        ull xa1 = val[va * 2 + 1];
        ull xb0 = val[vb * 2 + 0];
        ull xb1 = val[vb * 2 + 1];
        ull pa0 = __shfl_xor_sync(0xffffffffu, xa0, LM);
        ull pa1 = __shfl_xor_sync(0xffffffffu, xa1, LM);
        ull pb0 = __shfl_xor_sync(0xffffffffu, xb0, LM);
        ull pb1 = __shfl_xor_sync(0xffffffffu, xb1, LM);
        // butterflies
        ull ca = pk(q.x, q.x);
        ull sa = pk(q.y, q.y) ^ smask;
        ull cb = pk(q.z, q.z);
        ull sb = pk(q.w, q.w) ^ smask;
        val[va * 2 + 0] = f2fma(ca, xa0, f2mul(sa, pa0));
        val[va * 2 + 1] = f2fma(ca, xa1, f2mul(sa, pa1));
        val[vb * 2 + 0] = f2fma(cb, xb0, f2mul(sb, pb0));
        val[vb * 2 + 1] = f2fma(cb, xb1, f2mul(sb, pb1));
        if ((e & 3) == 3) cfence();
    }
}

// quintic WITHOUT trailing scale (folded into next layer's t0)
__device__ __forceinline__ void quintic(ull (&val)[64], int lane, int act) {
    const float4* __restrict__ qt = g_qt + act * 512;
    const ull C1875 = 0x3FF000003FF00000ULL;  // (1.875, 1.875)
    const ull CM125 = 0xBFA00000BFA00000ULL;  // (-1.25, -1.25)
    const ull C0375 = 0x3EC000003EC00000ULL;  // (0.375, 0.375)
#pragma unroll
    for (int e = 0; e < 16; e++) {
        float4 q = __ldg(qt + e * 32 + lane);
#pragma unroll
        for (int k = 0; k < 2; k++) {
            const int v = 2 * e + k;
            ull m2 = pk(k ? q.z : q.x, k ? q.z : q.x);
            ull nb2 = pk(k ? q.w : q.y, k ? q.w : q.y);
#pragma unroll
            for (int h = 0; h < 2; h++) {
                ull u = f2fma(val[v * 2 + h], m2, nb2);
                float lo, hi;
                unpk(u, lo, hi);
                lo = fminf(fmaxf(lo, -1.0f), 1.0f);
                hi = fminf(fmaxf(hi, -1.0f), 1.0f);
                u = pk(lo, hi);
                ull u2 = f2mul(u, u);
                ull p = f2fma(u2, C0375, CM125);
                p = f2fma(u2, p, C1875);
                val[v * 2 + h] = f2mul(u, p);
            }
        }
        if ((e & 3) == 3) cfence();
    }
}

__global__ void __launch_bounds__(128)
net_kernel(const float* __restrict__ X, float* __restrict__ Y) {
    const int lane = threadIdx.x & 31;
    const int w = blockIdx.x * 4 + (threadIdx.x >> 5);
    const long long row0 = (long long)w * 4;
    const float* __restrict__ xr0 = X + row0 * WIDTH;
    const float* __restrict__ xr1 = xr0 + WIDTH;
    const float* __restrict__ xr2 = xr1 + WIDTH;
    const float* __restrict__ xr3 = xr2 + WIDTH;

    ull val[64];

    // load: 4 rows; val[v*2+h]: h=0 -> (row0,row1), h=1 -> (row2,row3)
#pragma unroll
    for (int vhi = 0; vhi < 8; vhi++) {
        int off = vhi * 128 + lane * 4;
        int s = vhi * 4;
        {
            float4 a = *(const float4*)(xr0 + off);
            float4 b = *(const float4*)(xr1 + off);
            val[(s + 0) * 2 + 0] = pk(a.x, b.x);
            val[(s + 1) * 2 + 0] = pk(a.y, b.y);
            val[(s + 2) * 2 + 0] = pk(a.z, b.z);
            val[(s + 3) * 2 + 0] = pk(a.w, b.w);
        }
        cfence();
        {
            float4 c = *(const float4*)(xr2 + off);
            float4 d = *(const float4*)(xr3 + off);
            val[(s + 0) * 2 + 1] = pk(c.x, d.x);
            val[(s + 1) * 2 + 1] = pk(c.y, d.y);
            val[(s + 2) * 2 + 1] = pk(c.z, d.z);
            val[(s + 3) * 2 + 1] = pk(c.w, d.w);
        }
        cfence();
    }

#pragma unroll 1
    for (int layer = 0; layer < DEPTH; layer++) {
        const float4* __restrict__ bt = g_bt + layer * (BDEPTH * 256);
        t0_step(val, lane, g_t0 + layer * 512);  // t=0: p bit 9, scale-folded
        reg_step<8>(val, lane, bt + 1 * 256);    // t=1: p bit 8 (v bit 3)
        reg_step<4>(val, lane, bt + 2 * 256);    // t=2: p bit 7 (v bit 2)
        lane_step<16>(val, lane, bt + 3 * 256);  // t=3: p bit 6 (lane bit 4)
        lane_step<8>(val, lane, bt + 4 * 256);   // t=4: p bit 5
        lane_step<4>(val, lane, bt + 5 * 256);   // t=5: p bit 4
        lane_step<2>(val, lane, bt + 6 * 256);   // t=6: p bit 3
        lane_step<1>(val, lane, bt + 7 * 256);   // t=7: p bit 2 (lane bit 0)
        reg_step<2>(val, lane, bt + 8 * 256);    // t=8: p bit 1 (v bit 1)
        reg_step<1>(val, lane, bt + 9 * 256);    // t=9: p bit 0 (v bit 0)
        if (layer < DEPTH - 1) quintic(val, lane, layer);
    }

    // store (net permutation over 10 steps per layer is identity)
    float* __restrict__ yr0 = Y + row0 * WIDTH;
    float* __restrict__ yr1 = yr0 + WIDTH;
    float* __restrict__ yr2 = yr1 + WIDTH;
    float* __restrict__ yr3 = yr2 + WIDTH;
#pragma unroll
    for (int vhi = 0; vhi < 8; vhi++) {
        int off = vhi * 128 + lane * 4;
        int s = vhi * 4;
        {
            float4 a, b;
            unpk(val[(s + 0) * 2 + 0], a.x, b.x);
            unpk(val[(s + 1) * 2 + 0], a.y, b.y);
            unpk(val[(s + 2) * 2 + 0], a.z, b.z);
            unpk(val[(s + 3) * 2 + 0], a.w, b.w);
            *(float4*)(yr0 + off) = a;
            *(float4*)(yr1 + off) = b;
        }
        cfence();
        {
            float4 c, d;
            unpk(val[(s + 0) * 2 + 1], c.x, d.x);
            unpk(val[(s + 1) * 2 + 1], c.y, d.y);
            unpk(val[(s + 2) * 2 + 1], c.z, d.z);
            unpk(val[(s + 3) * 2 + 1], c.w, d.w);
            *(float4*)(yr2 + off) = c;
            *(float4*)(yr3 + off) = d;
        }
        cfence();
    }
}

extern "C" void kernel_launch(void* const* d_in, const int* in_sizes, int n_in,
                              void* d_out, int out_size) {
    const float* X     = (const float*)d_in[0];
    const float* bp    = (const float*)d_in[1];
    const float* bias  = (const float*)d_in[2];
    const float* slope = (const float*)d_in[3];
    const float* scale = (const float*)d_in[4];
    float* Y = (float*)d_out;

    prep_all<<<(BT_ELEMS + T0_ELEMS + QT_ELEMS + 255) / 256, 256>>>(bp, bias, slope, scale);
    // 4 rows/warp, 4 warps/CTA -> 16 rows per CTA; ~252 regs, 2 CTAs/SM
    net_kernel<<<BATCH / 16, 128>>>(X, Y);
}